// round 8
// baseline (speedup 1.0000x reference)
#include <cuda_runtime.h>

#define NB    4096
#define MAXKV 64
#define CTA   128            // 4 warps/CTA, warp per logical block
#define GRID  (NB / 4)       // 1024 CTAs -> all chip-resident (<=7 CTAs/SM)

// Scratch. g_rdy/g_done are reset by the last CTA each launch -> replay safe.
__device__ float2 g_pk[NB];     // (Σ p·keep, Σ keep) published per block
__device__ int    g_rdy[NB];    // readiness flag per block (0 at launch start)
__device__ float4 g_cta[GRID];  // per-CTA partials (bce, sup, gl, val)
__device__ int    g_done;       // last-CTA-done counter

__device__ __forceinline__ float warp_sum(float v) {
#pragma unroll
    for (int o = 16; o > 0; o >>= 1) v += __shfl_down_sync(0xffffffffu, v, o);
    return v;
}

__global__ void __launch_bounds__(CTA) fused(const float4* __restrict__ x4,
                                             const float4* __restrict__ t4,
                                             const uint4*  __restrict__ s4,
                                             const uint4*  __restrict__ i4,
                                             const uint2*  __restrict__ kvi2,
                                             const int*    __restrict__ kvn,
                                             float* __restrict__ out) {
    const int tid  = threadIdx.x;
    const int lane = tid & 31;
    const int wid  = tid >> 5;
    const int b    = blockIdx.x * 4 + wid;     // logical block
    const int vidx = b * 32 + lane;

    // ---- Front-batched loads: phase-B metadata first, then phase-A data (MLP=6) ----
    const uint2  jj = kvi2[vidx];              // neighbors 2*lane, 2*lane+1
    const int    nb = kvn[b];
    const float4 xv = x4[vidx];
    const float4 tv = t4[vidx];
    const uint4  sv = s4[vidx];
    const uint4  iv = i4[vidx];

    // ---- Phase A: per-node math -> 7 per-block scalars (stay in registers) ----
    float bce_s = 0.f, sup_s = 0.f, pk_s = 0.f, k_s = 0.f;
    float p1 = 0.f, p2 = 0.f, q = 0.f;
    {
        const float xs[4] = {xv.x, xv.y, xv.z, xv.w};
        const float ts[4] = {tv.x, tv.y, tv.z, tv.w};
        const unsigned int ss[4] = {sv.x, sv.y, sv.z, sv.w};
        const unsigned int is[4] = {iv.x, iv.y, iv.z, iv.w};
#pragma unroll
        for (int k = 0; k < 4; k++) {
            const float x = xs[k];
            const float e   = __expf(-fabsf(x));            // one exp for both
            const float inv = 1.0f / (1.0f + e);
            const float p   = (x >= 0.0f) ? inv : e * inv;
            const float sp  = fmaxf(x, 0.0f) + __logf(1.0f + e);
            const bool s    = ss[k] != 0u;
            const bool keep = is[k] == 0u;
            if (s)          { bce_s += sp - ts[k] * x; sup_s += 1.0f; }
            if (keep)       { pk_s  += p;              k_s   += 1.0f; }
            if (keep && !s) { p1 += p; p2 += p * p;    q     += 1.0f; }
        }
    }
    bce_s = warp_sum(bce_s); sup_s = warp_sum(sup_s);
    pk_s  = warp_sum(pk_s);  k_s   = warp_sum(k_s);
    p1    = warp_sum(p1);    p2    = warp_sum(p2);    q = warp_sum(q);

    // ---- Publish this block's gatherable pair, then set ready flag ----
    if (lane == 0) {
        g_pk[b] = make_float2(pk_s, k_s);
        __threadfence();                        // data before flag
        *((volatile int*)&g_rdy[b]) = 1;
    }

    // ---- Wait only for OUR 64 producers (all CTAs resident -> no deadlock) ----
    const bool use0 = (2 * lane)     < nb;
    const bool use1 = (2 * lane + 1) < nb;
    if (use0) { volatile int* f = &g_rdy[jj.x]; while (*f == 0) {} }
    if (use1) { volatile int* f = &g_rdy[jj.y]; while (*f == 0) {} }
    __threadfence();                            // acquire producers' g_pk writes

    // ---- Phase B: scalar gather -> n_mean; closed-form block loss ----
    float ns = 0.0f, nc = 0.0f;
    if (use0) { const float2 v = g_pk[jj.x]; ns += v.x; nc += v.y; }
    if (use1) { const float2 v = g_pk[jj.y]; ns += v.x; nc += v.y; }
    ns = warp_sum(ns); nc = warp_sum(nc);

    // ---- CTA-local reduction of (bce, sup, gl, val) ----
    __shared__ float4 sh[4];
    __shared__ int s_last;
    if (lane == 0) {
        const float m  = ns / fmaxf(nc, 1.0f);
        const float sq = p2 - 2.0f * m * p1 + q * m * m;   // Σ_unc (p-m)²
        const bool valid = (q > 0.0f) && (nc > 0.0f);
        sh[wid] = make_float4(bce_s, sup_s,
                              valid ? (sq / fmaxf(q, 1.0f)) : 0.0f,
                              valid ? 1.0f : 0.0f);
    }
    __syncthreads();
    if (tid == 0) {
        float4 r = sh[0];
#pragma unroll
        for (int i = 1; i < 4; i++) { r.x += sh[i].x; r.y += sh[i].y; r.z += sh[i].z; r.w += sh[i].w; }
        g_cta[blockIdx.x] = r;
        __threadfence();
        s_last = (atomicAdd(&g_done, 1) == GRID - 1) ? 1 : 0;
    }
    __syncthreads();
    if (!s_last) return;

    // ---- Last CTA: final reduction over 1024 per-CTA partials + state reset ----
    __threadfence();
    float a = 0.f, bb = 0.f, c = 0.f, d = 0.f;
    for (int i = tid; i < GRID; i += CTA) {
        const float4 r = g_cta[i];
        a += r.x; bb += r.y; c += r.z; d += r.w;
    }
    a = warp_sum(a); bb = warp_sum(bb); c = warp_sum(c); d = warp_sum(d);
    __shared__ float fin[4][4];
    if (lane == 0) { fin[0][wid] = a; fin[1][wid] = bb; fin[2][wid] = c; fin[3][wid] = d; }
    __syncthreads();
    if (tid == 0) {
        float A = 0.f, B = 0.f, C = 0.f, D = 0.f;
#pragma unroll
        for (int i = 0; i < 4; i++) { A += fin[0][i]; B += fin[1][i]; C += fin[2][i]; D += fin[3][i]; }
        const float loss_sup   = (B > 0.0f) ? (A / fmaxf(B, 1.0f)) : 0.0f;
        const float loss_graph = C / fmaxf(D, 1.0f);
        out[0] = loss_sup + 0.3f * loss_graph;
        g_done = 0;
    }
    // reset ready flags for next replay (no one reads them anymore this launch)
    for (int i = tid; i < NB; i += CTA) g_rdy[i] = 0;
}

extern "C" void kernel_launch(void* const* d_in, const int* in_sizes, int n_in,
                              void* d_out, int out_size) {
    const float4* x4   = (const float4*)d_in[0];  // logits   [524288] f32
    const float4* t4   = (const float4*)d_in[1];  // targets  [524288] f32
    const uint4*  s4   = (const uint4*)d_in[2];   // sup_mask  (4-byte bool)
    const uint4*  i4   = (const uint4*)d_in[3];   // ignore_mask
    const uint2*  kvi2 = (const uint2*)d_in[4];   // kv_indices [4096*64] as uint2
    const int*    kvn  = (const int*)d_in[5];     // kv_num_blocks [4096]
    (void)in_sizes; (void)n_in; (void)out_size;

    fused<<<GRID, CTA>>>(x4, t4, s4, i4, kvi2, kvn, (float*)d_out);
}

// round 9
// speedup vs baseline: 1.5496x; 1.5496x over previous
#include <cuda_runtime.h>

#define NB     4096
#define MAXKV  64
#define CTA    128              // 4 warps/CTA
#define GRIDAB (NB / 4)         // 1024 CTAs -> 4096 warps, warp per logical block

// Packed per-block scratch. Fully rewritten each launch (g_done reset by last user).
__device__ float2 g_pk[NB];    // (Σ p·keep, Σ keep)   <- gathered by neighbors
__device__ float2 g_bs[NB];    // (Σ bce·sup, Σ sup)
__device__ float4 g_own[NB];   // (Σ p·unc, Σ p²·unc, Σ unc, 0)
__device__ float2 g_gv[NB];    // (blk_loss·valid, valid)
__device__ int    g_done;      // last-CTA-done counter (zero-init, reset after use)

__device__ __forceinline__ float warp_sum(float v) {
#pragma unroll
    for (int o = 16; o > 0; o >>= 1) v += __shfl_down_sync(0xffffffffu, v, o);
    return v;
}

// ---------------- Kernel A: per-node math -> 7 packed per-block scalars ----------------
__global__ void __launch_bounds__(CTA) kernA(const float4* __restrict__ x4,
                                             const float4* __restrict__ t4,
                                             const uint4*  __restrict__ s4,
                                             const uint4*  __restrict__ i4) {
    // Let the dependent kernel (kernB) start launching immediately; it will
    // grid-sync before consuming our output.
    cudaTriggerProgrammaticLaunchCompletion();

    const int lane = threadIdx.x & 31;
    const int b    = blockIdx.x * 4 + (threadIdx.x >> 5);   // logical block
    const int vidx = b * 32 + lane;

    // Front-batched independent LDG.128 x4
    const float4 xv = x4[vidx];
    const float4 tv = t4[vidx];
    const uint4  sv = s4[vidx];
    const uint4  iv = i4[vidx];

    float bce_s = 0.f, sup_s = 0.f, pk_s = 0.f, k_s = 0.f;
    float p1 = 0.f, p2 = 0.f, q = 0.f;
    {
        const float xs[4] = {xv.x, xv.y, xv.z, xv.w};
        const float ts[4] = {tv.x, tv.y, tv.z, tv.w};
        const unsigned int ss[4] = {sv.x, sv.y, sv.z, sv.w};
        const unsigned int is[4] = {iv.x, iv.y, iv.z, iv.w};
#pragma unroll
        for (int k = 0; k < 4; k++) {
            const float x = xs[k];
            const float e   = __expf(-fabsf(x));            // one exp for softplus+sigmoid
            const float inv = 1.0f / (1.0f + e);
            const float p   = (x >= 0.0f) ? inv : e * inv;
            const float sp  = fmaxf(x, 0.0f) + __logf(1.0f + e);
            const bool s    = ss[k] != 0u;
            const bool keep = is[k] == 0u;
            if (s)          { bce_s += sp - ts[k] * x; sup_s += 1.0f; }
            if (keep)       { pk_s  += p;              k_s   += 1.0f; }
            if (keep && !s) { p1 += p; p2 += p * p;    q     += 1.0f; }
        }
    }
    bce_s = warp_sum(bce_s); sup_s = warp_sum(sup_s);
    pk_s  = warp_sum(pk_s);  k_s   = warp_sum(k_s);
    p1    = warp_sum(p1);    p2    = warp_sum(p2);    q = warp_sum(q);
    if (lane == 0) {
        g_pk[b]  = make_float2(pk_s, k_s);
        g_bs[b]  = make_float2(bce_s, sup_s);
        g_own[b] = make_float4(p1, p2, q, 0.0f);
    }
}

// ---------------- Kernel B: PDL-overlapped gather + closed-form loss + last-CTA reduce ----------------
__global__ void __launch_bounds__(CTA) kernB(const uint2* __restrict__ kvi2,
                                             const int*   __restrict__ kvn,
                                             float* __restrict__ out) {
    const int tid  = threadIdx.x;
    const int lane = tid & 31;
    const int b    = blockIdx.x * 4 + (tid >> 5);

    // These loads depend only on external inputs -> issue BEFORE the grid
    // dependency sync so their latency hides under kernA's execution.
    const uint2 jj = kvi2[b * 32 + lane];
    const int   nb = kvn[b];

    // Wait for kernA's results (g_pk/g_own/g_bs) to be globally visible.
    cudaGridDependencySynchronize();

    float ns = 0.0f, nc = 0.0f;
    if (2 * lane < nb)     { const float2 v = g_pk[jj.x]; ns += v.x; nc += v.y; }
    if (2 * lane + 1 < nb) { const float2 v = g_pk[jj.y]; ns += v.x; nc += v.y; }
    ns = warp_sum(ns); nc = warp_sum(nc);
    if (lane == 0) {
        const float  m  = ns / fmaxf(nc, 1.0f);
        const float4 ow = g_own[b];                              // (p1, p2, q, 0)
        const float  sq = ow.y - 2.0f * m * ow.x + ow.z * m * m; // Σ_unc (p-m)²
        const bool valid = (ow.z > 0.0f) && (nc > 0.0f);
        g_gv[b] = make_float2(valid ? (sq / fmaxf(ow.z, 1.0f)) : 0.0f,
                              valid ? 1.0f : 0.0f);
    }

    // ---- last-CTA-done final reduction ----
    __syncthreads();
    __shared__ int s_last;
    if (tid == 0) {
        __threadfence();                    // release this CTA's g_gv writes
        s_last = (atomicAdd(&g_done, 1) == GRIDAB - 1) ? 1 : 0;
    }
    __syncthreads();
    if (!s_last) return;

    __threadfence();                        // acquire all CTAs' g_gv writes
    float a = 0.f, bb = 0.f, c = 0.f, d = 0.f;
    for (int i = tid; i < NB; i += CTA) {
        const float2 bs = g_bs[i];
        const float2 gv = g_gv[i];
        a  += bs.x;
        bb += bs.y;
        c  += gv.x;
        d  += gv.y;
    }
    __shared__ float sh[4][4];
    a = warp_sum(a); bb = warp_sum(bb); c = warp_sum(c); d = warp_sum(d);
    const int w = tid >> 5;
    if (lane == 0) { sh[0][w] = a; sh[1][w] = bb; sh[2][w] = c; sh[3][w] = d; }
    __syncthreads();
    if (tid == 0) {
        float A = 0.f, B = 0.f, C = 0.f, D = 0.f;
#pragma unroll
        for (int i = 0; i < 4; i++) { A += sh[0][i]; B += sh[1][i]; C += sh[2][i]; D += sh[3][i]; }
        const float loss_sup   = (B > 0.0f) ? (A / fmaxf(B, 1.0f)) : 0.0f;
        const float loss_graph = C / fmaxf(D, 1.0f);
        out[0] = loss_sup + 0.3f * loss_graph;
        g_done = 0;   // reset for next graph replay
    }
}

extern "C" void kernel_launch(void* const* d_in, const int* in_sizes, int n_in,
                              void* d_out, int out_size) {
    const float4* x4   = (const float4*)d_in[0];  // logits   [524288] f32
    const float4* t4   = (const float4*)d_in[1];  // targets  [524288] f32
    const uint4*  s4   = (const uint4*)d_in[2];   // sup_mask  (4-byte bool)
    const uint4*  i4   = (const uint4*)d_in[3];   // ignore_mask
    const uint2*  kvi2 = (const uint2*)d_in[4];   // kv_indices [4096*64] as uint2
    const int*    kvn  = (const int*)d_in[5];     // kv_num_blocks [4096]
    (void)in_sizes; (void)n_in; (void)out_size;

    kernA<<<GRIDAB, CTA>>>(x4, t4, s4, i4);

    // kernB with programmatic dependent launch: overlaps its ramp + index loads
    // with kernA; correctness via cudaGridDependencySynchronize() inside kernB.
    cudaLaunchConfig_t cfg = {};
    cfg.gridDim  = dim3(GRIDAB, 1, 1);
    cfg.blockDim = dim3(CTA, 1, 1);
    cfg.dynamicSmemBytes = 0;
    cudaLaunchAttribute attr[1];
    attr[0].id = cudaLaunchAttributeProgrammaticStreamSerialization;
    attr[0].val.programmaticStreamSerializationAllowed = 1;
    cfg.attrs = attr;
    cfg.numAttrs = 1;
    cudaLaunchKernelEx(&cfg, kernB, kvi2, kvn, (float*)d_out);
}